// round 10
// baseline (speedup 1.0000x reference)
#include <cuda_runtime.h>
#include <cuda_bf16.h>
#include <math.h>

// HMM forward, linear domain, power-of-2 rescale. 16 clusters x 8 CTAs;
// CTA owns 64-row slice of W (bf16 pairs, smem). Per-slice mbarriers: warp w
// waits (ACQUIRE.cluster) only on producer slice w/2, then copies+computes.
// Publish: stcg -> full __syncthreads -> 8 lane-parallel release arrives
// (R7-proven ordering; no run-ahead).

#define HH 512
#define VV 50257
#define TT 512
#define NT 512

using ull = unsigned long long;
using u32 = unsigned int;

#define CLUSTER_SYNC() do { \
  asm volatile("barrier.cluster.arrive.aligned;" ::: "memory"); \
  asm volatile("barrier.cluster.wait.aligned;"   ::: "memory"); \
} while (0)

__device__ float g_X[2][16][2048];     // [par][cluster][kp*8 + b*2 + hi]

__device__ __forceinline__ ull ffma2(ull a, ull b, ull c) {
  ull d;
  asm("fma.rn.f32x2 %0, %1, %2, %3;" : "=l"(d) : "l"(a), "l"(b), "l"(c));
  return d;
}
__device__ __forceinline__ float psum2(ull u) {
  return __uint_as_float((unsigned)u) + __uint_as_float((unsigned)(u >> 32));
}
__device__ __forceinline__ u32 smem_u32(const void* p) {
  u32 a;
  asm("{ .reg .u64 t; cvta.to.shared.u64 t, %1; cvt.u32.u64 %0, t; }" : "=r"(a) : "l"(p));
  return a;
}
__device__ __forceinline__ u32 mapa_u32(u32 local, int rank) {
  u32 r;
  asm("mapa.shared::cluster.u32 %0, %1, %2;" : "=r"(r) : "r"(local), "r"(rank));
  return r;
}
// ACQUIRE wait: pairs with producer's release arrive -> stcg data guaranteed
// visible before the post-wait ldcg (fixes the R8 stale-slice race).
__device__ __forceinline__ void mbar_wait_acq(u32 addr, u32 ph) {
  asm volatile(
    "{\n\t.reg .pred P;\n\t"
    "W%=:\n\t"
    "mbarrier.try_wait.parity.acquire.cluster.shared::cta.b64 P, [%0], %1, 0x989680;\n\t"
    "@!P bra W%=;\n\t}"
    :: "r"(addr), "r"(ph) : "memory");
}
// bf162 (lo=W[2kp], hi=W[2kp+1]) -> packed f32x2 (exact: f32 = bf16 << 16)
__device__ __forceinline__ ull bf2_to_f32x2(u32 wb) {
  u32 lo = wb << 16;
  u32 hi = wb & 0xffff0000u;
  return (ull)lo | ((ull)hi << 32);
}

extern __shared__ u32 sWb[];   // 64KB: bf162 pairs [kp:256][row:64]

__global__ void __cluster_dims__(8, 1, 1) __launch_bounds__(NT, 1)
hmm_main(const float* __restrict__ A, const float* __restrict__ beta,
         const float* __restrict__ gamma, const int* __restrict__ ids,
         float* __restrict__ out) {
  __shared__ __align__(16) float  xs[2048];     // x vec [kp*8 + b*2 + hi]
  __shared__ __align__(16) float4 red[16][64];  // [warp][row] 4-batch partials
  __shared__ float  wmx[16][4];                 // [warp][b] local x maxes
  __shared__ int    sids[4][TT];
  __shared__ float  smax2[16];
  __shared__ __align__(8) ull mbars[8];         // one per producer slice

  const int tid  = threadIdx.x;
  const int myq  = blockIdx.x & 7;
  const int cl   = blockIdx.x >> 3;
  const int base = myq * 64;
  const int warp = tid >> 5, lane = tid & 31;

  // ---- prologue: bf16 W slice into smem; per-slice mbars (count=1) ----
  for (int idx = tid; idx < 64 * 256; idx += NT) {
    int row = idx & 63, kp = idx >> 6;
    float v0 = A[(2 * kp) * HH + base + row] + 1e-12f;
    float v1 = A[(2 * kp + 1) * HH + base + row] + 1e-12f;
    sWb[kp * 64 + row] =
        *(u32*)&(__nv_bfloat162&)*(__nv_bfloat162[]){
            __float22bfloat162_rn(make_float2(v0, v1))};
  }
  for (int i = tid; i < 4 * TT; i += NT) {
    int b0 = i >> 9, t0 = i & (TT - 1);
    sids[b0][t0] = ids[(cl * 4 + b0) * TT + t0];
  }
  if (tid < 8)
    asm volatile("mbarrier.init.shared.b64 [%0], %1;"
                 :: "r"(smem_u32(&mbars[tid])), "r"(1u) : "memory");
  __syncthreads();

  // ---- init: full alpha0, M0, x1 = exp(alpha0 - M0) (rank 0 publishes) ----
  float M0[4];
  {
    float* a0s = (float*)red;   // 4096-float scratch
    for (int idx = tid; idx < 4 * HH; idx += NT) {
      int bb = idx >> 9, k = idx & 511;
      a0s[idx] = __logf(gamma[k]) + __ldg(&beta[(size_t)k * VV + sids[bb][0]]);
    }
    __syncthreads();
    {
      int bb = warp >> 2, seg = warp & 3;
      float m = -3.4e38f;
      #pragma unroll
      for (int i = 0; i < 4; i++)
        m = fmaxf(m, a0s[bb * 512 + seg * 128 + i * 32 + lane]);
      #pragma unroll
      for (int o = 16; o > 0; o >>= 1)
        m = fmaxf(m, __shfl_xor_sync(0xffffffffu, m, o));
      if (lane == 0) smax2[warp] = m;
    }
    __syncthreads();
    #pragma unroll
    for (int bb = 0; bb < 4; bb++)
      M0[bb] = fmaxf(fmaxf(smax2[4 * bb], smax2[4 * bb + 1]),
                     fmaxf(smax2[4 * bb + 2], smax2[4 * bb + 3]));
    if (myq == 0) {
      for (int idx = tid; idx < 4 * HH; idx += NT) {
        int bb = idx >> 9, k = idx & 511;
        __stcg(&g_X[1][cl][(k >> 1) * 8 + bb * 2 + (k & 1)],
               __expf(a0s[idx] - M0[bb]));
      }
    }
    __syncthreads();
  }
  CLUSTER_SYNC();

  const bool act = (tid < 256);
  const int  b   = (tid >> 6) & 3;
  const int  r   = tid & 63;
  const int  h   = base + r;
  const float C0 = M0[b];
  int Cexp = 0;
  const u32 my_mbar  = smem_u32(&mbars[warp >> 1]);  // slice this warp reads
  const u32 pub_mbar = smem_u32(&mbars[myq]);        // slice this CTA writes
  u32 wph = 0;

  float e_cur = 0.0f;
  if (act) e_cur = __expf(__ldg(&beta[(size_t)h * VV + sids[b][1]]));

  for (int t = 1; t < TT; t++) {
    const int par = t & 1;

    float bsel_next = 0.0f;
    if (act && t + 1 < TT)
      bsel_next = __ldg(&beta[(size_t)h * VV + sids[b][t + 1]]);

    // per-warp gate: only the producer slice this warp consumes (ACQUIRE)
    if (t >= 2) { mbar_wait_acq(my_mbar, wph); wph ^= 1; }

    // copy own 512B of x (exactly what this warp's matvec reads)
    float mlo, mhi;
    {
      const float4* src = (const float4*)&g_X[par][cl][0];
      float4 v = __ldcg(src + warp * 32 + lane);
      *(float4*)(xs + (warp * 32 + lane) * 4) = v;
      mlo = fmaxf(v.x, v.y);   // batches (0,1) even lanes / (2,3) odd lanes
      mhi = fmaxf(v.z, v.w);
      __syncwarp();
    }

    // matvec: warp owns kp in [16w, 16w+16); rows {lane, lane+32}, 4 batches
    ull a0 = 0, a1 = 0, a2 = 0, a3 = 0, a4 = 0, a5 = 0, a6 = 0, a7 = 0;
    {
      const u32* wp = sWb + warp * (16 * 64) + lane;
      const ulonglong2* xp = (const ulonglong2*)xs + warp * 32;
      #pragma unroll
      for (int kpi = 0; kpi < 16; kpi++) {
        ull w0 = bf2_to_f32x2(wp[0]);     // row lane
        ull w1 = bf2_to_f32x2(wp[32]);    // row lane+32
        ulonglong2 xa = xp[0];            // batches 0,1 (broadcast)
        ulonglong2 xb = xp[1];            // batches 2,3
        wp += 64; xp += 2;
        a0 = ffma2(w0, xa.x, a0);
        a1 = ffma2(w0, xa.y, a1);
        a2 = ffma2(w0, xb.x, a2);
        a3 = ffma2(w0, xb.y, a3);
        a4 = ffma2(w1, xa.x, a4);
        a5 = ffma2(w1, xa.y, a5);
        a6 = ffma2(w1, xb.x, a6);
        a7 = ffma2(w1, xb.y, a7);
      }
    }
    red[warp][lane]      = make_float4(psum2(a0), psum2(a1), psum2(a2), psum2(a3));
    red[warp][lane + 32] = make_float4(psum2(a4), psum2(a5), psum2(a6), psum2(a7));

    // warp-local per-batch max (off the pre-matvec path)
    #pragma unroll
    for (int o = 2; o <= 16; o <<= 1) {
      mlo = fmaxf(mlo, __shfl_xor_sync(0xffffffffu, mlo, o));
      mhi = fmaxf(mhi, __shfl_xor_sync(0xffffffffu, mhi, o));
    }
    if (lane == 0) { wmx[warp][0] = mlo; wmx[warp][1] = mhi; }
    if (lane == 1) { wmx[warp][2] = mlo; wmx[warp][3] = mhi; }

    __syncthreads();   // red/wmx complete

    if (act) {
      float Ma = fmaxf(fmaxf(wmx[0][b], wmx[1][b]), fmaxf(wmx[2][b], wmx[3][b]));
      float Mb = fmaxf(fmaxf(wmx[4][b], wmx[5][b]), fmaxf(wmx[6][b], wmx[7][b]));
      float Mc = fmaxf(fmaxf(wmx[8][b], wmx[9][b]), fmaxf(wmx[10][b], wmx[11][b]));
      float Md = fmaxf(fmaxf(wmx[12][b], wmx[13][b]), fmaxf(wmx[14][b], wmx[15][b]));
      float M  = fmaxf(fmaxf(Ma, Mb), fmaxf(Mc, Md));

      const float* rp = (const float*)red + r * 4 + b;
      float s0 = rp[0]        + rp[256];
      float s1 = rp[2 * 256]  + rp[3 * 256];
      float s2 = rp[4 * 256]  + rp[5 * 256];
      float s3 = rp[6 * 256]  + rp[7 * 256];
      float s4 = rp[8 * 256]  + rp[9 * 256];
      float s5 = rp[10 * 256] + rp[11 * 256];
      float s6 = rp[12 * 256] + rp[13 * 256];
      float s7 = rp[14 * 256] + rp[15 * 256];
      float z = ((s0 + s1) + (s2 + s3)) + ((s4 + s5) + (s6 + s7));

      int eb = (int)(__float_as_uint(M) >> 23);             // biased exponent
      float invM = __uint_as_float((u32)(254 - eb) << 23);  // exact 2^(127-eb)
      Cexp += eb - 127;

      float u = z * e_cur * invM;

      if (t == TT - 1) {
        double o = (double)__logf(u) + (double)C0
                 + (double)Cexp * 0.6931471805599453;
        out[(cl * 4 + b) * HH + h] = (float)o;
      } else {
        __stcg(&g_X[par ^ 1][cl][(h >> 1) * 8 + b * 2 + (h & 1)], u);
        e_cur = __expf(bsel_next);
      }
    }
    __syncthreads();   // all act stcg issued + red free for next step

    if (t < TT - 1 && warp == 0 && lane < 8) {
      u32 ra = mapa_u32(pub_mbar, lane);   // parallel remote arrives
      asm volatile("mbarrier.arrive.release.cluster.shared::cluster.b64 _, [%0];"
                   :: "r"(ra) : "memory");
    }
  }
}

extern "C" void kernel_launch(void* const* d_in, const int* in_sizes, int n_in,
                              void* d_out, int out_size) {
  const float* A     = (const float*)d_in[0];   // alpha_exp (H,H)
  const float* beta  = (const float*)d_in[1];   // (H,V)
  const float* gamma = (const float*)d_in[2];   // (1,H)
  const int*   ids   = (const int*)d_in[3];     // (B,T) int32
  float* out = (float*)d_out;                   // (B,H) f32

  cudaFuncSetAttribute(hmm_main, cudaFuncAttributeMaxDynamicSharedMemorySize,
                       96 * 1024);
  hmm_main<<<128, NT, 65536>>>(A, beta, gamma, ids, out);
}

// round 11
// speedup vs baseline: 2.0643x; 2.0643x over previous
#include <cuda_runtime.h>
#include <cuda_bf16.h>
#include <math.h>

// HMM forward, linear domain, power-of-2 rescale. 32 clusters x 4 CTAs;
// cluster owns 2 batches; CTA owns 128-row slice of W (bf16 pairs, 128KB
// smem). Depth-2 emission prefetch (beta gathers hit DRAM; 2 steps of slack).
// Exchange: stcg -> __syncthreads -> 4 lane-parallel release arrives;
// consumers use per-slice ACQUIRE waits. Power-of-2 rescale, Cexp integer.

#define HH 512
#define VV 50257
#define TT 512
#define NT 512
#define RPC 128      // rows per CTA
#define NCL 32       // clusters

using ull = unsigned long long;
using u32 = unsigned int;

#define CLUSTER_SYNC() do { \
  asm volatile("barrier.cluster.arrive.aligned;" ::: "memory"); \
  asm volatile("barrier.cluster.wait.aligned;"   ::: "memory"); \
} while (0)

__device__ float g_X[2][NCL][1024];   // [par][cluster][kp*4 + b*2 + hi]

__device__ __forceinline__ ull ffma2(ull a, ull b, ull c) {
  ull d;
  asm("fma.rn.f32x2 %0, %1, %2, %3;" : "=l"(d) : "l"(a), "l"(b), "l"(c));
  return d;
}
__device__ __forceinline__ float psum2(ull u) {
  return __uint_as_float((unsigned)u) + __uint_as_float((unsigned)(u >> 32));
}
__device__ __forceinline__ u32 smem_u32(const void* p) {
  u32 a;
  asm("{ .reg .u64 t; cvta.to.shared.u64 t, %1; cvt.u32.u64 %0, t; }" : "=r"(a) : "l"(p));
  return a;
}
__device__ __forceinline__ u32 mapa_u32(u32 local, int rank) {
  u32 r;
  asm("mapa.shared::cluster.u32 %0, %1, %2;" : "=r"(r) : "r"(local), "r"(rank));
  return r;
}
__device__ __forceinline__ void mbar_wait_acq(u32 addr, u32 ph) {
  asm volatile(
    "{\n\t.reg .pred P;\n\t"
    "W%=:\n\t"
    "mbarrier.try_wait.parity.acquire.cluster.shared::cta.b64 P, [%0], %1, 0x989680;\n\t"
    "@!P bra W%=;\n\t}"
    :: "r"(addr), "r"(ph) : "memory");
}
// bf162 (lo=W[2kp], hi=W[2kp+1]) -> packed f32x2 (exact widening)
__device__ __forceinline__ ull bf2_to_f32x2(u32 wb) {
  u32 lo = wb << 16;
  u32 hi = wb & 0xffff0000u;
  return (ull)lo | ((ull)hi << 32);
}

extern __shared__ u32 sWb[];   // 128KB: bf162 pairs [kp:256][row:128]

__global__ void __cluster_dims__(4, 1, 1) __launch_bounds__(NT, 1)
hmm_main(const float* __restrict__ A, const float* __restrict__ beta,
         const float* __restrict__ gamma, const int* __restrict__ ids,
         float* __restrict__ out) {
  __shared__ __align__(16) float  xs[1024];       // x vec [kp*4 + b*2 + hi]
  __shared__ __align__(16) float2 red[16][RPC];   // [warp][row] = (b0,b1)
  __shared__ float  wmx[16][2];                   // [warp][b] local x maxes
  __shared__ int    sids[2][TT];
  __shared__ float  smax2[16];
  __shared__ __align__(8) ull mbars[4];           // one per producer slice

  const int tid  = threadIdx.x;
  const int myq  = blockIdx.x & 3;    // cluster rank == row-slice id
  const int cl   = blockIdx.x >> 2;   // cluster id
  const int base = myq * RPC;
  const int warp = tid >> 5, lane = tid & 31;

  // ---- prologue: bf16 W slice (rows [base, base+128), all K) ----
  for (int idx = tid; idx < RPC * 256; idx += NT) {
    int row = idx & (RPC - 1), kp = idx >> 7;
    float v0 = A[(2 * kp) * HH + base + row] + 1e-12f;
    float v1 = A[(2 * kp + 1) * HH + base + row] + 1e-12f;
    __nv_bfloat162 bf = __float22bfloat162_rn(make_float2(v0, v1));
    sWb[kp * RPC + row] = *(u32*)&bf;
  }
  for (int i = tid; i < 2 * TT; i += NT) {
    int b0 = i >> 9, t0 = i & (TT - 1);
    sids[b0][t0] = ids[(cl * 2 + b0) * TT + t0];
  }
  if (tid < 4)
    asm volatile("mbarrier.init.shared.b64 [%0], %1;"
                 :: "r"(smem_u32(&mbars[tid])), "r"(1u) : "memory");
  __syncthreads();

  // ---- init: full alpha0 (2 batches), M0, x1 (rank 0 publishes) ----
  float M0[2];
  {
    float* a0s = (float*)red;   // 2048-float scratch region (only 1024 used)
    for (int idx = tid; idx < 2 * HH; idx += NT) {
      int bb = idx >> 9, k = idx & 511;
      a0s[idx] = __logf(gamma[k]) + __ldg(&beta[(size_t)k * VV + sids[bb][0]]);
    }
    __syncthreads();
    {
      int bb = warp >> 3, seg = warp & 7;   // warp covers 64 values of batch bb
      float m = fmaxf(a0s[bb * 512 + seg * 64 + lane],
                      a0s[bb * 512 + seg * 64 + 32 + lane]);
      #pragma unroll
      for (int o = 16; o > 0; o >>= 1)
        m = fmaxf(m, __shfl_xor_sync(0xffffffffu, m, o));
      if (lane == 0) smax2[warp] = m;
    }
    __syncthreads();
    #pragma unroll
    for (int bb = 0; bb < 2; bb++) {
      float m = smax2[bb * 8];
      #pragma unroll
      for (int s = 1; s < 8; s++) m = fmaxf(m, smax2[bb * 8 + s]);
      M0[bb] = m;
    }
    if (myq == 0) {
      for (int idx = tid; idx < 2 * HH; idx += NT) {
        int bb = idx >> 9, k = idx & 511;
        __stcg(&g_X[1][cl][(k >> 1) * 4 + bb * 2 + (k & 1)],
               __expf(a0s[idx] - M0[bb]));
      }
    }
    __syncthreads();
  }
  CLUSTER_SYNC();

  const bool act = (tid < 256);
  const int  b   = tid >> 7;            // batch (0/1) for act threads
  const int  r   = tid & (RPC - 1);     // row-in-slice
  const int  h   = base + r;
  const float C0 = M0[b & 1];
  int Cexp = 0;
  const u32 my_mbar  = smem_u32(&mbars[warp >> 2]);  // slice this warp reads
  const u32 pub_mbar = smem_u32(&mbars[myq]);        // slice this CTA writes
  u32 wph = 0;

  // depth-2 emission prefetch: e_cur for t=1; bq = logit for t=2
  float e_cur = 0.0f, bq = 0.0f;
  if (act) {
    e_cur = __expf(__ldg(&beta[(size_t)h * VV + sids[b][1]]));
    bq = __ldg(&beta[(size_t)h * VV + sids[b][2]]);
  }

  for (int t = 1; t < TT; t++) {
    const int par = t & 1;

    // issue logit load for t+2 (two full steps of slack vs DRAM latency)
    float bnew = 0.0f;
    if (act && t + 2 < TT)
      bnew = __ldg(&beta[(size_t)h * VV + sids[b][t + 2]]);

    // per-warp gate on this warp's producer slice (ACQUIRE pairs w/ release)
    if (t >= 2) { mbar_wait_acq(my_mbar, wph); wph ^= 1; }

    // copy own 256B of x (exactly what this warp's matvec reads): idx->(kp,b)
    float mlo, mhi;
    {
      const float2* src = (const float2*)&g_X[par][cl][0];
      int idx = warp * 32 + lane;              // kp = idx>>1, bx = idx&1
      float2 v = __ldcg(src + idx);
      ((float2*)xs)[idx] = v;
      mlo = fmaxf(v.x, v.y);                   // max for this (kp, bx)
      mhi = 0.0f; (void)mhi;
      __syncwarp();
      // per-warp per-batch max: lanes alternate bx; xor 2..16 keeps parity
      #pragma unroll
      for (int o = 2; o <= 16; o <<= 1)
        mlo = fmaxf(mlo, __shfl_xor_sync(0xffffffffu, mlo, o));
      if (lane == 0) wmx[warp][0] = mlo;
      if (lane == 1) wmx[warp][1] = mlo;
    }

    // matvec: warp owns kp in [16w, 16w+16); rows {lane,+32,+64,+96} x 2 b
    ull a0 = 0, a1 = 0, a2 = 0, a3 = 0, a4 = 0, a5 = 0, a6 = 0, a7 = 0;
    {
      const u32* wp = sWb + (warp * 16) * RPC + lane;
      const ulonglong2* xp = (const ulonglong2*)xs + warp * 16;
      #pragma unroll
      for (int kpi = 0; kpi < 16; kpi++) {
        ull w0 = bf2_to_f32x2(wp[0]);
        ull w1 = bf2_to_f32x2(wp[32]);
        ull w2 = bf2_to_f32x2(wp[64]);
        ull w3 = bf2_to_f32x2(wp[96]);
        ulonglong2 xv = xp[kpi];      // .x = batch0 pair, .y = batch1 pair
        wp += RPC;
        a0 = ffma2(w0, xv.x, a0);
        a1 = ffma2(w0, xv.y, a1);
        a2 = ffma2(w1, xv.x, a2);
        a3 = ffma2(w1, xv.y, a3);
        a4 = ffma2(w2, xv.x, a4);
        a5 = ffma2(w2, xv.y, a5);
        a6 = ffma2(w3, xv.x, a6);
        a7 = ffma2(w3, xv.y, a7);
      }
    }
    red[warp][lane]      = make_float2(psum2(a0), psum2(a1));
    red[warp][lane + 32] = make_float2(psum2(a2), psum2(a3));
    red[warp][lane + 64] = make_float2(psum2(a4), psum2(a5));
    red[warp][lane + 96] = make_float2(psum2(a6), psum2(a7));

    __syncthreads();   // red/wmx complete

    if (act) {
      // cluster-consistent per-batch scale (redundant local compute)
      float Ma = fmaxf(fmaxf(wmx[0][b], wmx[1][b]), fmaxf(wmx[2][b], wmx[3][b]));
      float Mb = fmaxf(fmaxf(wmx[4][b], wmx[5][b]), fmaxf(wmx[6][b], wmx[7][b]));
      float Mc = fmaxf(fmaxf(wmx[8][b], wmx[9][b]), fmaxf(wmx[10][b], wmx[11][b]));
      float Md = fmaxf(fmaxf(wmx[12][b], wmx[13][b]), fmaxf(wmx[14][b], wmx[15][b]));
      float M  = fmaxf(fmaxf(Ma, Mb), fmaxf(Mc, Md));

      const float* rp = (const float*)red + r * 2 + b;
      float s0 = rp[0]        + rp[256];
      float s1 = rp[2 * 256]  + rp[3 * 256];
      float s2 = rp[4 * 256]  + rp[5 * 256];
      float s3 = rp[6 * 256]  + rp[7 * 256];
      float s4 = rp[8 * 256]  + rp[9 * 256];
      float s5 = rp[10 * 256] + rp[11 * 256];
      float s6 = rp[12 * 256] + rp[13 * 256];
      float s7 = rp[14 * 256] + rp[15 * 256];
      float z = ((s0 + s1) + (s2 + s3)) + ((s4 + s5) + (s6 + s7));

      int eb = (int)(__float_as_uint(M) >> 23);             // biased exponent
      float invM = __uint_as_float((u32)(254 - eb) << 23);  // exact 2^(127-eb)
      Cexp += eb - 127;

      float u = z * e_cur * invM;

      if (t == TT - 1) {
        double o = (double)__logf(u) + (double)C0
                 + (double)Cexp * 0.6931471805599453;
        out[(cl * 2 + b) * HH + h] = (float)o;
      } else {
        __stcg(&g_X[par ^ 1][cl][(h >> 1) * 4 + b * 2 + (h & 1)], u);
        e_cur = __expf(bq);   // emission for t+1, loaded 2 steps ago
        bq = bnew;
      }
    }
    __syncthreads();   // all act stcg issued + red free for next step

    if (t < TT - 1 && warp == 0 && lane < 4) {
      u32 ra = mapa_u32(pub_mbar, lane);   // parallel remote arrives
      asm volatile("mbarrier.arrive.release.cluster.shared::cluster.b64 _, [%0];"
                   :: "r"(ra) : "memory");
    }
  }
}

extern "C" void kernel_launch(void* const* d_in, const int* in_sizes, int n_in,
                              void* d_out, int out_size) {
  const float* A     = (const float*)d_in[0];   // alpha_exp (H,H)
  const float* beta  = (const float*)d_in[1];   // (H,V)
  const float* gamma = (const float*)d_in[2];   // (1,H)
  const int*   ids   = (const int*)d_in[3];     // (B,T) int32
  float* out = (float*)d_out;                   // (B,H) f32

  cudaFuncSetAttribute(hmm_main, cudaFuncAttributeMaxDynamicSharedMemorySize,
                       132 * 1024);
  hmm_main<<<128, NT, 131072>>>(A, beta, gamma, ids, out);
}

// round 13
// speedup vs baseline: 2.5311x; 1.2261x over previous
#include <cuda_runtime.h>
#include <cuda_bf16.h>
#include <math.h>

// HMM forward, linear domain, power-of-2 rescale, mma.sync (HMMA) matvec with
// W fragments RESIDENT IN REGISTERS (64 u32/thread, loaded once).
// 32 clusters x 4 CTAs; cluster owns 2 batches; CTA owns a 128-row W slice.
// Per step: acquire-wait -> ldcg x -> cvt bf16 -> STS B-pairs -> bar ->
// B-frag LDS + 16 mma.sync/warp (2 acc chains) -> STS partials -> bar ->
// epilogue (tid<256): z, power-of-2 rescale, stcg, named bar, release arrives.
// Depth-2 beta prefetch. All R10-proven sync machinery kept.

#define HH 512
#define VV 50257
#define TT 512
#define NT 512
#define RPC 128
#define NCL 32

using ull = unsigned long long;
using u32 = unsigned int;

#define CLUSTER_SYNC() do { \
  asm volatile("barrier.cluster.arrive.aligned;" ::: "memory"); \
  asm volatile("barrier.cluster.wait.aligned;"   ::: "memory"); \
} while (0)

__device__ float g_X[2][NCL][1024];   // [par][cluster][kp*4 + b*2 + hi]

__device__ __forceinline__ u32 smem_u32(const void* p) {
  u32 a;
  asm("{ .reg .u64 t; cvta.to.shared.u64 t, %1; cvt.u32.u64 %0, t; }" : "=r"(a) : "l"(p));
  return a;
}
__device__ __forceinline__ u32 mapa_u32(u32 local, int rank) {
  u32 r;
  asm("mapa.shared::cluster.u32 %0, %1, %2;" : "=r"(r) : "r"(local), "r"(rank));
  return r;
}
__device__ __forceinline__ void mbar_wait_acq(u32 addr, u32 ph) {
  asm volatile(
    "{\n\t.reg .pred P;\n\t"
    "W%=:\n\t"
    "mbarrier.try_wait.parity.acquire.cluster.shared::cta.b64 P, [%0], %1, 0x989680;\n\t"
    "@!P bra W%=;\n\t}"
    :: "r"(addr), "r"(ph) : "memory");
}
__device__ __forceinline__ u32 pkbf(float a, float b) {
  __nv_bfloat162 t = __float22bfloat162_rn(make_float2(a, b));
  return *(u32*)&t;
}
#define MMA16816(c0, c1, c2, c3, a0, a1, a2, a3, b0, b1) \
  asm volatile( \
    "mma.sync.aligned.m16n8k16.row.col.f32.bf16.bf16.f32 " \
    "{%0,%1,%2,%3}, {%4,%5,%6,%7}, {%8,%9}, {%0,%1,%2,%3};" \
    : "+f"(c0), "+f"(c1), "+f"(c2), "+f"(c3) \
    : "r"(a0), "r"(a1), "r"(a2), "r"(a3), "r"(b0), "r"(b1))

__global__ void __cluster_dims__(4, 1, 1) __launch_bounds__(NT, 1)
hmm_main(const float* __restrict__ A, const float* __restrict__ beta,
         const float* __restrict__ gamma, const int* __restrict__ ids,
         float* __restrict__ out) {
  __shared__ __align__(16) u32    xsb[2][272];     // bf16x2 x pairs, padded
  __shared__ __align__(16) float2 red2[2][128];    // [khalf][row] = (b0,b1)
  __shared__ float wmx[2][16][2];                  // [par][warp][b]
  __shared__ __align__(16) float a0s[1024];
  __shared__ int   sids[2][TT];
  __shared__ float smax2[16];
  __shared__ __align__(8) ull mbars[4];

  const int tid  = threadIdx.x;
  const int myq  = blockIdx.x & 3;     // cluster rank == row-slice
  const int cl   = blockIdx.x >> 2;    // cluster id
  const int base = myq * RPC;
  const int warp = tid >> 5, lane = tid & 31;
  const int mt = warp & 7, kh = warp >> 3;   // m-tile, k-half of this warp
  const int r4 = lane >> 2, tig = lane & 3;

  // ---- prologue: W fragments into registers (persistent, 64 u32) ----
  u32 Areg[64];
  {
    const int row0 = base + mt * 16 + r4;
    #pragma unroll
    for (int kt = 0; kt < 16; kt++) {
      const int k0 = kh * 256 + kt * 16 + 2 * tig;
      const float* p0 = A + (size_t)k0 * HH;
      float w00 = p0[row0]            + 1e-12f;
      float w01 = p0[HH + row0]       + 1e-12f;
      float w10 = p0[row0 + 8]        + 1e-12f;
      float w11 = p0[HH + row0 + 8]   + 1e-12f;
      float w20 = p0[8 * HH + row0]   + 1e-12f;
      float w21 = p0[9 * HH + row0]   + 1e-12f;
      float w30 = p0[8 * HH + row0 + 8] + 1e-12f;
      float w31 = p0[9 * HH + row0 + 8] + 1e-12f;
      Areg[kt * 4 + 0] = pkbf(w00, w01);
      Areg[kt * 4 + 1] = pkbf(w10, w11);
      Areg[kt * 4 + 2] = pkbf(w20, w21);
      Areg[kt * 4 + 3] = pkbf(w30, w31);
    }
  }
  for (int i = tid; i < 2 * TT; i += NT) {
    int b0 = i >> 9, t0 = i & (TT - 1);
    sids[b0][t0] = ids[(cl * 2 + b0) * TT + t0];
  }
  if (tid < 4)
    asm volatile("mbarrier.init.shared.b64 [%0], %1;"
                 :: "r"(smem_u32(&mbars[tid])), "r"(1u) : "memory");
  __syncthreads();

  // ---- init: alpha0 (2 batches), M0, x1 (rank 0 publishes) ----
  float M0[2];
  {
    for (int idx = tid; idx < 2 * HH; idx += NT) {
      int bb = idx >> 9, k = idx & 511;
      a0s[idx] = __logf(gamma[k]) + __ldg(&beta[(size_t)k * VV + sids[bb][0]]);
    }
    __syncthreads();
    {
      int bb = warp >> 3, seg = warp & 7;
      float m = fmaxf(a0s[bb * 512 + seg * 64 + lane],
                      a0s[bb * 512 + seg * 64 + 32 + lane]);
      #pragma unroll
      for (int o = 16; o > 0; o >>= 1)
        m = fmaxf(m, __shfl_xor_sync(0xffffffffu, m, o));
      if (lane == 0) smax2[warp] = m;
    }
    __syncthreads();
    #pragma unroll
    for (int bb = 0; bb < 2; bb++) {
      float m = smax2[bb * 8];
      #pragma unroll
      for (int s = 1; s < 8; s++) m = fmaxf(m, smax2[bb * 8 + s]);
      M0[bb] = m;
    }
    if (myq == 0) {
      for (int idx = tid; idx < 2 * HH; idx += NT) {
        int bb = idx >> 9, k = idx & 511;
        __stcg(&g_X[1][cl][(k >> 1) * 4 + bb * 2 + (k & 1)],
               __expf(a0s[idx] - M0[bb]));
      }
    }
    __syncthreads();
  }
  CLUSTER_SYNC();

  const bool act = (tid < 256);
  const int  b   = tid >> 7;           // batch (0/1) for act threads
  const int  r   = tid & (RPC - 1);    // row-in-slice
  const int  h   = base + r;
  const float C0 = M0[b & 1];
  int Cexp = 0;
  const u32 my_mbar  = smem_u32(&mbars[warp >> 2]);
  const u32 pub_mbar = smem_u32(&mbars[myq]);
  u32 wph = 0;

  // depth-2 emission prefetch
  float e_cur = 0.0f, bq = 0.0f;
  if (act) {
    e_cur = __expf(__ldg(&beta[(size_t)h * VV + sids[b][1]]));
    bq = __ldg(&beta[(size_t)h * VV + sids[b][2]]);
  }

  for (int t = 1; t < TT; t++) {
    const int par = t & 1;

    float bnew = 0.0f;
    if (act && t + 2 < TT)
      bnew = __ldg(&beta[(size_t)h * VV + sids[b][t + 2]]);

    if (t >= 2) { mbar_wait_acq(my_mbar, wph); wph ^= 1; }

    // copy x: lane owns pair idx -> (kp = idx>>1, bx = idx&1); cvt -> xsb
    {
      const int idx = warp * 32 + lane;
      float2 v = __ldcg(&((const float2*)&g_X[par][cl][0])[idx]);
      u32 pair;
      asm("cvt.rn.satfinite.bf16x2.f32 %0, %1, %2;" : "=r"(pair) : "f"(v.y), "f"(v.x));
      xsb[idx & 1][idx >> 1] = pair;
      float mlo = fmaxf(v.x, v.y);
      #pragma unroll
      for (int o = 2; o <= 16; o <<= 1)
        mlo = fmaxf(mlo, __shfl_xor_sync(0xffffffffu, mlo, o));
      if (lane == 0) wmx[par][warp][0] = mlo;
      if (lane == 1) wmx[par][warp][1] = mlo;
    }
    __syncthreads();   // bar1: xsb + wmx complete

    // 16 mma.sync per warp, 2 interleaved accumulator chains
    float c0 = 0.f, c1 = 0.f, c2 = 0.f, c3 = 0.f;
    float d0 = 0.f, d1 = 0.f, d2 = 0.f, d3 = 0.f;
    {
      const int kpb = kh * 128;
      #pragma unroll
      for (int kt = 0; kt < 16; kt += 2) {
        u32 b0 = 0, b1 = 0, b2 = 0, b3 = 0;
        if (lane < 8) {             // col = r4 (0/1 real batches); rest zero
          b0 = xsb[r4][kpb + kt * 8 + tig];
          b1 = xsb[r4][kpb + kt * 8 + tig + 4];
          b2 = xsb[r4][kpb + kt * 8 + 8 + tig];
          b3 = xsb[r4][kpb + kt * 8 + 8 + tig + 4];
        }
        MMA16816(c0, c1, c2, c3,
                 Areg[kt * 4 + 0], Areg[kt * 4 + 1],
                 Areg[kt * 4 + 2], Areg[kt * 4 + 3], b0, b1);
        MMA16816(d0, d1, d2, d3,
                 Areg[kt * 4 + 4], Areg[kt * 4 + 5],
                 Areg[kt * 4 + 6], Areg[kt * 4 + 7], b2, b3);
      }
    }
    // cols 0,1 live in threads with tig==0: c0/c1 = row r4, c2/c3 = row r4+8
    if (tig == 0) {
      red2[kh][mt * 16 + r4]     = make_float2(c0 + d0, c1 + d1);
      red2[kh][mt * 16 + r4 + 8] = make_float2(c2 + d2, c3 + d3);
    }
    __syncthreads();   // bar2: red2 complete

    if (act) {
      const float* rk0 = (const float*)&red2[0][0];
      const float* rk1 = (const float*)&red2[1][0];
      float z = rk0[r * 2 + b] + rk1[r * 2 + b];

      // cluster-consistent per-batch power-of-2 scale
      float Ma = fmaxf(fmaxf(wmx[par][0][b], wmx[par][1][b]),
                       fmaxf(wmx[par][2][b], wmx[par][3][b]));
      float Mb = fmaxf(fmaxf(wmx[par][4][b], wmx[par][5][b]),
                       fmaxf(wmx[par][6][b], wmx[par][7][b]));
      float Mc = fmaxf(fmaxf(wmx[par][8][b], wmx[par][9][b]),
                       fmaxf(wmx[par][10][b], wmx[par][11][b]));
      float Md = fmaxf(fmaxf(wmx[par][12][b], wmx[par][13][b]),
                       fmaxf(wmx[par][14][b], wmx[par][15][b]));
      float M  = fmaxf(fmaxf(Ma, Mb), fmaxf(Mc, Md));

      int eb = (int)(__float_as_uint(M) >> 23);
      float invM = __uint_as_float((u32)(254 - eb) << 23);
      Cexp += eb - 127;

      float u = z * e_cur * invM;

      if (t == TT - 1) {
        out[(cl * 2 + b) * HH + h] =
            (float)((double)__logf(u) + (double)C0
                    + (double)Cexp * 0.6931471805599453);
      } else {
        __stcg(&g_X[par ^ 1][cl][(h >> 1) * 4 + b * 2 + (h & 1)], u);
        e_cur = __expf(bq);
        bq = bnew;
        asm volatile("bar.sync 1, 256;" ::: "memory");   // act threads only
        if (warp == 0 && lane < 4) {
          u32 ra = mapa_u32(pub_mbar, lane);
          asm volatile("mbarrier.arrive.release.cluster.shared::cluster.b64 _, [%0];"
                       :: "r"(ra) : "memory");
        }
      }
    }
    // warps 8-15 run ahead into the next step's wait/copy
  }
}

extern "C" void kernel_launch(void* const* d_in, const int* in_sizes, int n_in,
                              void* d_out, int out_size) {
  const float* A     = (const float*)d_in[0];   // alpha_exp (H,H)
  const float* beta  = (const float*)d_in[1];   // (H,V)
  const float* gamma = (const float*)d_in[2];   // (1,H)
  const int*   ids   = (const int*)d_in[3];     // (B,T) int32
  float* out = (float*)d_out;                   // (B,H) f32

  hmm_main<<<128, NT>>>(A, beta, gamma, ids, out);
}

// round 14
// speedup vs baseline: 3.4651x; 1.3690x over previous
#include <cuda_runtime.h>
#include <cuda_bf16.h>
#include <math.h>

// HMM forward, linear domain, power-of-2 rescale, HMMA matvec (W in regs),
// DSMEM-push x exchange (no L2 state). 32 clusters x 4 CTAs, 2 batches each.
// Per step: acquire-wait(mbars2[par]) -> B-frag LDS from LOCAL xsb[par] ->
// 16 mma.sync/warp -> syncthreads -> epilogue: z, M from local wmxp[par],
// u = z*e*2^-m; push bf16 pairs + warp maxes into all 4 CTAs' [par^1]
// buffers via st.shared::cluster -> named bar -> 4 remote release arrives.

#define HH 512
#define VV 50257
#define TT 512
#define NT 512
#define RPC 128
#define NCL 32

using ull = unsigned long long;
using u32 = unsigned int;

#define CLUSTER_SYNC() do { \
  asm volatile("barrier.cluster.arrive.aligned;" ::: "memory"); \
  asm volatile("barrier.cluster.wait.aligned;"   ::: "memory"); \
} while (0)

__device__ __forceinline__ u32 smem_u32(const void* p) {
  u32 a;
  asm("{ .reg .u64 t; cvta.to.shared.u64 t, %1; cvt.u32.u64 %0, t; }" : "=r"(a) : "l"(p));
  return a;
}
__device__ __forceinline__ u32 mapa_u32(u32 local, int rank) {
  u32 r;
  asm("mapa.shared::cluster.u32 %0, %1, %2;" : "=r"(r) : "r"(local), "r"(rank));
  return r;
}
__device__ __forceinline__ void mbar_wait_acq(u32 addr, u32 ph) {
  asm volatile(
    "{\n\t.reg .pred P;\n\t"
    "W%=:\n\t"
    "mbarrier.try_wait.parity.acquire.cluster.shared::cta.b64 P, [%0], %1, 0x989680;\n\t"
    "@!P bra W%=;\n\t}"
    :: "r"(addr), "r"(ph) : "memory");
}
__device__ __forceinline__ u32 pkbf(float a, float b) {
  __nv_bfloat162 t = __float22bfloat162_rn(make_float2(a, b));
  return *(u32*)&t;
}
#define MMA16816(c0, c1, c2, c3, a0, a1, a2, a3, b0, b1) \
  asm volatile( \
    "mma.sync.aligned.m16n8k16.row.col.f32.bf16.bf16.f32 " \
    "{%0,%1,%2,%3}, {%4,%5,%6,%7}, {%8,%9}, {%0,%1,%2,%3};" \
    : "+f"(c0), "+f"(c1), "+f"(c2), "+f"(c3) \
    : "r"(a0), "r"(a1), "r"(a2), "r"(a3), "r"(b0), "r"(b1))

__global__ void __cluster_dims__(4, 1, 1) __launch_bounds__(NT, 1)
hmm_main(const float* __restrict__ A, const float* __restrict__ beta,
         const float* __restrict__ gamma, const int* __restrict__ ids,
         float* __restrict__ out) {
  __shared__ __align__(16) u32    xsb[2][2][264];  // [par][b][kp] bf16x2, pad
  __shared__ __align__(16) float2 red2[2][128];    // [khalf][row] = (b0,b1)
  __shared__ float wmxp[2][4][4][2];               // [par][slice][quarter][b]
  __shared__ __align__(16) float a0s[1024];
  __shared__ int   sids[2][TT];
  __shared__ float smax2[16];
  __shared__ __align__(8) ull mbars2[2];           // per-parity, count=4

  const int tid  = threadIdx.x;
  const int myq  = blockIdx.x & 3;     // cluster rank == row-slice
  const int cl   = blockIdx.x >> 2;    // cluster id
  const int base = myq * RPC;
  const int warp = tid >> 5, lane = tid & 31;
  const int mt = warp & 7, kh = warp >> 3;   // m-tile, k-half
  const int r4 = lane >> 2, tig = lane & 3;

  // ---- prologue: W fragments into registers (persistent, 64 u32) ----
  u32 Areg[64];
  {
    const int row0 = base + mt * 16 + r4;
    #pragma unroll
    for (int kt = 0; kt < 16; kt++) {
      const int k0 = kh * 256 + kt * 16 + 2 * tig;
      const float* p0 = A + (size_t)k0 * HH;
      float w00 = p0[row0]              + 1e-12f;
      float w01 = p0[HH + row0]         + 1e-12f;
      float w10 = p0[row0 + 8]          + 1e-12f;
      float w11 = p0[HH + row0 + 8]     + 1e-12f;
      float w20 = p0[8 * HH + row0]     + 1e-12f;
      float w21 = p0[9 * HH + row0]     + 1e-12f;
      float w30 = p0[8 * HH + row0 + 8] + 1e-12f;
      float w31 = p0[9 * HH + row0 + 8] + 1e-12f;
      Areg[kt * 4 + 0] = pkbf(w00, w01);
      Areg[kt * 4 + 1] = pkbf(w10, w11);
      Areg[kt * 4 + 2] = pkbf(w20, w21);
      Areg[kt * 4 + 3] = pkbf(w30, w31);
    }
  }
  for (int i = tid; i < 2 * TT; i += NT) {
    int b0 = i >> 9, t0 = i & (TT - 1);
    sids[b0][t0] = ids[(cl * 2 + b0) * TT + t0];
  }
  if (tid < 2)
    asm volatile("mbarrier.init.shared.b64 [%0], %1;"
                 :: "r"(smem_u32(&mbars2[tid])), "r"(4u) : "memory");
  __syncthreads();

  // ---- init: alpha0 (2 batches), M0; x1 + wmxp[1] built LOCALLY ----
  float M0[2];
  {
    for (int idx = tid; idx < 2 * HH; idx += NT) {
      int bb = idx >> 9, k = idx & 511;
      a0s[idx] = __logf(gamma[k]) + __ldg(&beta[(size_t)k * VV + sids[bb][0]]);
    }
    __syncthreads();
    {
      int bb = warp >> 3, seg = warp & 7;
      float m = fmaxf(a0s[bb * 512 + seg * 64 + lane],
                      a0s[bb * 512 + seg * 64 + 32 + lane]);
      #pragma unroll
      for (int o = 16; o > 0; o >>= 1)
        m = fmaxf(m, __shfl_xor_sync(0xffffffffu, m, o));
      if (lane == 0) smax2[warp] = m;
    }
    __syncthreads();
    #pragma unroll
    for (int bb = 0; bb < 2; bb++) {
      float m = smax2[bb * 8];
      #pragma unroll
      for (int s = 1; s < 8; s++) m = fmaxf(m, smax2[bb * 8 + s]);
      M0[bb] = m;
    }
    // x1 pairs (every CTA, local; no cross-CTA distribution needed at t=1)
    {
      int bx = tid >> 8, kp = tid & 255;
      float v0 = __expf(a0s[bx * 512 + 2 * kp]     - M0[bx]);
      float v1 = __expf(a0s[bx * 512 + 2 * kp + 1] - M0[bx]);
      xsb[1][bx][kp] = pkbf(v0, v1);
    }
    // wmxp[1][q][qr][b] = max over rows [q*128+qr*32, +32) of x1[b]
    {
      #pragma unroll
      for (int bb = 0; bb < 2; bb++) {
        float m = a0s[bb * 512 + warp * 32 + lane];
        #pragma unroll
        for (int o = 16; o > 0; o >>= 1)
          m = fmaxf(m, __shfl_xor_sync(0xffffffffu, m, o));
        if (lane == 0) wmxp[1][warp >> 2][warp & 3][bb] = __expf(m - M0[bb]);
      }
    }
    __syncthreads();
  }
  CLUSTER_SYNC();

  const bool act = (tid < 256);
  const int  b   = tid >> 7;           // batch (0/1) for act threads
  const int  r   = tid & (RPC - 1);    // row-in-slice
  const int  h   = base + r;
  const float C0 = M0[b & 1];
  int Cexp = 0;
  const u32 xsb_u  = smem_u32(xsb);
  const u32 wmxp_u = smem_u32(wmxp);
  const u32 mb0_u  = smem_u32(&mbars2[0]);
  int phs0 = 0, phs1 = 0;

  // depth-2 emission prefetch
  float e_cur = 0.0f, bq = 0.0f;
  if (act) {
    e_cur = __expf(__ldg(&beta[(size_t)h * VV + sids[b][1]]));
    bq = __ldg(&beta[(size_t)h * VV + sids[b][2]]);
  }

  for (int t = 1; t < TT; t++) {
    const int par = t & 1;

    float bnew = 0.0f;
    if (act && t + 2 < TT)
      bnew = __ldg(&beta[(size_t)h * VV + sids[b][t + 2]]);

    if (t >= 2) {
      if (par == 0) { mbar_wait_acq(mb0_u, phs0); phs0 ^= 1; }
      else          { mbar_wait_acq(mb0_u + 8, phs1); phs1 ^= 1; }
    }

    // 16 mma.sync per warp, B fragments straight from local xsb[par]
    float c0 = 0.f, c1 = 0.f, c2 = 0.f, c3 = 0.f;
    float d0 = 0.f, d1 = 0.f, d2 = 0.f, d3 = 0.f;
    {
      const int kpb = kh * 128;
      #pragma unroll
      for (int kt = 0; kt < 16; kt += 2) {
        u32 b0 = 0, b1 = 0, b2 = 0, b3 = 0;
        if (lane < 8) {             // col = r4 (2 real batches); rest zero
          b0 = xsb[par][r4][kpb + kt * 8 + tig];
          b1 = xsb[par][r4][kpb + kt * 8 + tig + 4];
          b2 = xsb[par][r4][kpb + kt * 8 + 8 + tig];
          b3 = xsb[par][r4][kpb + kt * 8 + 8 + tig + 4];
        }
        MMA16816(c0, c1, c2, c3,
                 Areg[kt * 4 + 0], Areg[kt * 4 + 1],
                 Areg[kt * 4 + 2], Areg[kt * 4 + 3], b0, b1);
        MMA16816(d0, d1, d2, d3,
                 Areg[kt * 4 + 4], Areg[kt * 4 + 5],
                 Areg[kt * 4 + 6], Areg[kt * 4 + 7], b2, b3);
      }
    }
    if (tig == 0) {
      red2[kh][mt * 16 + r4]     = make_float2(c0 + d0, c1 + d1);
      red2[kh][mt * 16 + r4 + 8] = make_float2(c2 + d2, c3 + d3);
    }
    __syncthreads();   // red2 complete; also: all reads of xsb[par] done

    if (act) {
      const float* rk0 = (const float*)&red2[0][0];
      const float* rk1 = (const float*)&red2[1][0];
      float z = rk0[r * 2 + b] + rk1[r * 2 + b];

      // cluster-consistent per-batch power-of-2 scale (local wmxp[par])
      float M = wmxp[par][0][0][b];
      #pragma unroll
      for (int q = 0; q < 4; q++)
        #pragma unroll
        for (int qr = 0; qr < 4; qr++)
          M = fmaxf(M, wmxp[par][q][qr][b]);

      int eb = (int)(__float_as_uint(M) >> 23);
      float invM = __uint_as_float((u32)(254 - eb) << 23);
      Cexp += eb - 127;

      float u = z * e_cur * invM;

      if (t == TT - 1) {
        out[(cl * 2 + b) * HH + h] =
            (float)((double)__logf(u) + (double)C0
                    + (double)Cexp * 0.6931471805599453);
      } else {
        // push bf16 pair to all 4 CTAs' xsb[par^1][b][h>>1]
        float partner = __shfl_xor_sync(0xffffffffu, u, 1);
        u32 pair = (r & 1) ? pkbf(partner, u) : pkbf(u, partner);
        u32 loff = xsb_u + (u32)((((par ^ 1) * 2 + b) * 264 + (h >> 1)) * 4);
        int rk0i = (r & 1) ? 2 : 0;
        u32 ra0 = mapa_u32(loff, rk0i);
        u32 ra1 = mapa_u32(loff, rk0i + 1);
        asm volatile("st.shared::cluster.u32 [%0], %1;" :: "r"(ra0), "r"(pair) : "memory");
        asm volatile("st.shared::cluster.u32 [%0], %1;" :: "r"(ra1), "r"(pair) : "memory");

        // push warp max to all 4 CTAs' wmxp[par^1][myq][qr][b]
        float wm = u;
        #pragma unroll
        for (int o = 16; o > 0; o >>= 1)
          wm = fmaxf(wm, __shfl_xor_sync(0xffffffffu, wm, o));
        if (lane < 4) {
          u32 woff = wmxp_u +
              (u32)(((((par ^ 1) * 4 + myq) * 4 + ((warp & 3))) * 2 + b) * 4);
          u32 wra = mapa_u32(woff, lane);
          asm volatile("st.shared::cluster.f32 [%0], %1;" :: "r"(wra), "f"(wm) : "memory");
        }

        e_cur = __expf(bq);
        bq = bnew;
        asm volatile("bar.sync 1, 256;" ::: "memory");   // act pushes issued
        if (warp == 0 && lane < 4) {
          u32 ra = mapa_u32(mb0_u + (u32)((par ^ 1) * 8), lane);
          asm volatile("mbarrier.arrive.release.cluster.shared::cluster.b64 _, [%0];"
                       :: "r"(ra) : "memory");
        }
      }
    }
    // warps 8-15 run ahead into the next step's wait + MMA
  }
}

extern "C" void kernel_launch(void* const* d_in, const int* in_sizes, int n_in,
                              void* d_out, int out_size) {
  const float* A     = (const float*)d_in[0];   // alpha_exp (H,H)
  const float* beta  = (const float*)d_in[1];   // (H,V)
  const float* gamma = (const float*)d_in[2];   // (1,H)
  const int*   ids   = (const int*)d_in[3];     // (B,T) int32
  float* out = (float*)d_out;                   // (B,H) f32

  hmm_main<<<128, NT>>>(A, beta, gamma, ids, out);
}